// round 3
// baseline (speedup 1.0000x reference)
#include <cuda_runtime.h>
#include <cuda_fp16.h>
#include <cuda_bf16.h>
#include <cuda_fp8.h>
#include <cstdint>

// ---------------------------------------------------------------------------
// Problem constants
// ---------------------------------------------------------------------------
constexpr int T_DIM = 8192;
constexpr int H_DIM = 4096;
constexpr float EPS = 1e-6f;

// Scratch (static __device__ arrays: allocation-free per harness rules).
// NOTE: these symbols must ONLY be referenced from device code. Passing them
// as kernel arguments from host code passes the HOST shadow address, which on
// GB300 (ATS) is silently dereferenceable -> wrong-memory writes, no fault.
__device__ float          g_resid[(size_t)T_DIM * H_DIM];   // 128 MB
__device__ float          g_z[(size_t)T_DIM * H_DIM];       // 128 MB
__device__ __nv_bfloat16  g_a[(size_t)T_DIM * H_DIM];       // 64 MB (dequantized activations)
__device__ __nv_bfloat16  g_b[(size_t)H_DIM * H_DIM];       // 32 MB (dequantized weights, per-i)

// ---------------------------------------------------------------------------
// Quantization emulation (bit-matches the reference's fp32 op sequence)
// ---------------------------------------------------------------------------

// fp4 e2m1 round: searchsorted(mids, a, 'right') => a >= midpoint rounds UP.
__device__ __forceinline__ float fp4_round_ref(float v) {
    float a = fminf(fabsf(v), 6.0f);
    float q;
    if      (a >= 5.0f)  q = 6.0f;
    else if (a >= 3.5f)  q = 4.0f;
    else if (a >= 2.5f)  q = 3.0f;
    else if (a >= 1.75f) q = 2.0f;
    else if (a >= 1.25f) q = 1.5f;
    else if (a >= 0.75f) q = 1.0f;
    else if (a >= 0.25f) q = 0.5f;
    else                 q = 0.0f;
    return copysignf(q, v);
}

// fp8 e4m3fn round-to-nearest-even (matches jnp astype(float8_e4m3fn))
__device__ __forceinline__ float fp8_e4m3_round(float x) {
    __nv_fp8_storage_t r = __nv_cvt_float_to_fp8(x, __NV_SATFINITE, __NV_E4M3);
    __half_raw hr = __nv_cvt_fp8_to_halfraw(r, __NV_E4M3);
    return __half2float(__half(hr));
}

// Quantize one 16-element block of y (already in regs), write dequantized bf16.
// Dequant value q*sc has <=6 significand bits -> exact in bf16.
__device__ __forceinline__ void quant_block16(const float* y, float gs,
                                              __nv_bfloat16* dst) {
    float amax = 0.0f;
#pragma unroll
    for (int j = 0; j < 16; j++) amax = fmaxf(amax, fabsf(y[j]));
    float sc = fminf(__fmul_rn(__fdiv_rn(amax, 6.0f), gs), 448.0f);
    sc = fp8_e4m3_round(sc);
    if (sc > 0.0f) {
#pragma unroll
        for (int j = 0; j < 16; j++) {
            float r = __fdiv_rn(__fmul_rn(y[j], gs), sc);
            float q = fp4_round_ref(r);
            dst[j] = __float2bfloat16(__fmul_rn(q, sc));  // exact
        }
    } else {
#pragma unroll
        for (int j = 0; j < 16; j++) dst[j] = __float2bfloat16(0.0f);
    }
}

// ---------------------------------------------------------------------------
// Fused rownorm kernel. One block (256 threads) per row.
//   mode 0: x = relu(src);           resid=x; y=rmsnorm(x); quant->g_a
//   mode 1: x = g_z*alpha + g_resid; resid=x; y=rmsnorm(x); quant->g_a
//   mode 2: x = g_z*alpha + g_resid;          y=rmsnorm(x); write y (f32) -> yout
// ---------------------------------------------------------------------------
__global__ __launch_bounds__(256)
void rownorm_quant_kernel(int mode,
                          const float* __restrict__ src,
                          const float* __restrict__ norm_w,
                          const float* __restrict__ a_gs,
                          const float* __restrict__ wg_prev,
                          const float* __restrict__ ag_prev,
                          float* __restrict__ yout) {
    __shared__ float sx[H_DIM];
    __shared__ float warpsum[8];
    __shared__ float s_rstd;

    const int row = blockIdx.x;
    const int tid = threadIdx.x;
    const size_t base = (size_t)row * H_DIM;

    float alpha = 0.0f;
    if (mode != 0)
        alpha = __fdiv_rn(1.0f, __fmul_rn(*wg_prev, *ag_prev));

    // Phase 1: build x, accumulate sum of squares (coalesced)
    float ss = 0.0f;
    for (int j = tid; j < H_DIM; j += 256) {
        float x;
        if (mode == 0) {
            x = fmaxf(src[base + j], 0.0f);
        } else {
            float z = g_z[base + j];
            float r = g_resid[base + j];
            x = __fadd_rn(__fmul_rn(z, alpha), r);
        }
        if (mode != 2) g_resid[base + j] = x;
        sx[j] = x;
        ss = fmaf(x, x, ss);
    }

    // Phase 2: block reduce -> rstd
#pragma unroll
    for (int o = 16; o > 0; o >>= 1) ss += __shfl_xor_sync(0xffffffffu, ss, o);
    if ((tid & 31) == 0) warpsum[tid >> 5] = ss;
    __syncthreads();
    if (tid == 0) {
        float t = 0.0f;
#pragma unroll
        for (int i = 0; i < 8; i++) t += warpsum[i];
        float mean = t * (1.0f / (float)H_DIM);   // exact (power of 2)
        s_rstd = __frsqrt_rn(__fadd_rn(mean, EPS));
    }
    __syncthreads();
    const float rstd = s_rstd;

    // Phase 3: y = (x*rstd)*w ; one quant block of 16 per thread
    const int b = tid;                 // 256 blocks of 16 = 4096
    float y[16];
#pragma unroll
    for (int j = 0; j < 16; j++) {
        float xv = sx[b * 16 + j];
        y[j] = __fmul_rn(__fmul_rn(xv, rstd), norm_w[b * 16 + j]);
    }
    if (mode == 2) {
#pragma unroll
        for (int j = 0; j < 16; j++) yout[base + b * 16 + j] = y[j];
    } else {
        quant_block16(y, *a_gs, &g_a[base + b * 16]);
    }
}

// ---------------------------------------------------------------------------
// Weight quantization: one block per weight row, bit-exact vs. reference.
// ---------------------------------------------------------------------------
__global__ __launch_bounds__(256)
void wquant_kernel(const float* __restrict__ w, const float* __restrict__ gs_ptr) {
    __shared__ float sx[H_DIM];
    const int row = blockIdx.x;
    const int tid = threadIdx.x;
    const size_t base = (size_t)row * H_DIM;
    for (int j = tid; j < H_DIM; j += 256) sx[j] = w[base + j];
    __syncthreads();
    const float gs = *gs_ptr;
    float y[16];
#pragma unroll
    for (int j = 0; j < 16; j++) y[j] = sx[tid * 16 + j];
    quant_block16(y, gs, &g_b[base + tid * 16]);
}

// ---------------------------------------------------------------------------
// bf16 GEMM: g_z[t][n] = sum_k g_a[t][k] * g_b[n][k]   (C = A @ B^T)
// 128x128x32 block tiles, 8 warps (32x64 warp tiles), mma.m16n8k16,
// cp.async double buffering. Padded smem stride (40 bf16) => conflict-free
// 32-bit fragment loads and 16B-aligned cp.async targets.
// Output symbol g_z referenced from DEVICE code only (see note above).
// ---------------------------------------------------------------------------
constexpr int BM = 128, BN = 128, BK = 32;
constexpr int STRIDE = 40;  // bf16 elems per smem tile row (80B, 16B aligned)

__device__ __forceinline__ void cp_async16(uint32_t saddr, const void* gaddr) {
    asm volatile("cp.async.cg.shared.global [%0], [%1], 16;" :: "r"(saddr), "l"(gaddr));
}
__device__ __forceinline__ void cp_commit() { asm volatile("cp.async.commit_group;"); }
__device__ __forceinline__ void cp_wait0()  { asm volatile("cp.async.wait_group 0;"); }

__device__ __forceinline__ void mma16816(float* d, const uint32_t* a, const uint32_t* b) {
    asm volatile(
        "mma.sync.aligned.m16n8k16.row.col.f32.bf16.bf16.f32 "
        "{%0,%1,%2,%3}, {%4,%5,%6,%7}, {%8,%9}, {%0,%1,%2,%3};"
        : "+f"(d[0]), "+f"(d[1]), "+f"(d[2]), "+f"(d[3])
        : "r"(a[0]), "r"(a[1]), "r"(a[2]), "r"(a[3]), "r"(b[0]), "r"(b[1]));
}

__global__ __launch_bounds__(256)
void gemm_kernel() {
    const __nv_bfloat16* __restrict__ A = g_a;
    const __nv_bfloat16* __restrict__ B = g_b;
    float* __restrict__ C = g_z;                 // device-side symbol reference
    constexpr int K = H_DIM, N = H_DIM;

    __shared__ __align__(16) __nv_bfloat16 sA[2][BM * STRIDE];
    __shared__ __align__(16) __nv_bfloat16 sB[2][BN * STRIDE];

    const int tid = threadIdx.x;
    const int blockM = blockIdx.y * BM;
    const int blockN = blockIdx.x * BN;

    // ---- load mapping: 16B per thread per half-tile, 2 halves (rows r0, r0+64)
    const int chunk = tid & 3;        // which 16B of the 64B row
    const int r0    = tid >> 2;       // 0..63
    const __nv_bfloat16* gA0 = A + (size_t)(blockM + r0) * K + chunk * 8;
    const __nv_bfloat16* gB0 = B + (size_t)(blockN + r0) * K + chunk * 8;
    const int sOff = r0 * STRIDE + chunk * 8;

    // ---- compute mapping
    const int lane = tid & 31, wid = tid >> 5;
    const int g  = lane >> 2;         // groupID 0..7
    const int t4 = lane & 3;          // threadID-in-group 0..3
    const int wm = (wid & 3) * 32;    // warp row offset (4 warps along M)
    const int wn = (wid >> 2) * 64;   // warp col offset (2 warps along N)

    float acc[2][8][4];
#pragma unroll
    for (int mt = 0; mt < 2; mt++)
#pragma unroll
        for (int nt = 0; nt < 8; nt++)
#pragma unroll
            for (int r = 0; r < 4; r++) acc[mt][nt][r] = 0.0f;

    auto load_tile = [&](int buf, int k0) {
        uint32_t sa = (uint32_t)__cvta_generic_to_shared(&sA[buf][sOff]);
        uint32_t sb = (uint32_t)__cvta_generic_to_shared(&sB[buf][sOff]);
        cp_async16(sa,                      gA0 + k0);
        cp_async16(sa + 64 * STRIDE * 2,    gA0 + (size_t)64 * K + k0);
        cp_async16(sb,                      gB0 + k0);
        cp_async16(sb + 64 * STRIDE * 2,    gB0 + (size_t)64 * K + k0);
    };

    load_tile(0, 0); cp_commit();
    cp_wait0(); __syncthreads();

    const int KT = K / BK;  // 128
    for (int kt = 0; kt < KT; kt++) {
        const int cbuf = kt & 1;
        if (kt + 1 < KT) { load_tile(cbuf ^ 1, (kt + 1) * BK); cp_commit(); }

#pragma unroll
        for (int kk = 0; kk < BK; kk += 16) {
            uint32_t a_frag[2][4];
            uint32_t b_frag[8][2];
#pragma unroll
            for (int mt = 0; mt < 2; mt++) {
                int r = wm + mt * 16 + g;
                const uint32_t* p0 = (const uint32_t*)&sA[cbuf][r * STRIDE + kk + t4 * 2];
                const uint32_t* p1 = (const uint32_t*)&sA[cbuf][(r + 8) * STRIDE + kk + t4 * 2];
                a_frag[mt][0] = p0[0];
                a_frag[mt][1] = p1[0];
                a_frag[mt][2] = p0[4];   // +8 bf16 elems
                a_frag[mt][3] = p1[4];
            }
#pragma unroll
            for (int nt = 0; nt < 8; nt++) {
                int n = wn + nt * 8 + g;
                const uint32_t* p = (const uint32_t*)&sB[cbuf][n * STRIDE + kk + t4 * 2];
                b_frag[nt][0] = p[0];
                b_frag[nt][1] = p[4];
            }
#pragma unroll
            for (int mt = 0; mt < 2; mt++)
#pragma unroll
                for (int nt = 0; nt < 8; nt++)
                    mma16816(acc[mt][nt], a_frag[mt], b_frag[nt]);
        }

        if (kt + 1 < KT) cp_wait0();
        __syncthreads();
    }

    // Epilogue: coalesced float2 stores
#pragma unroll
    for (int mt = 0; mt < 2; mt++) {
#pragma unroll
        for (int nt = 0; nt < 8; nt++) {
            int r = blockM + wm + mt * 16 + g;
            int c = blockN + wn + nt * 8 + t4 * 2;
            *(float2*)&C[(size_t)r * N + c]       = make_float2(acc[mt][nt][0], acc[mt][nt][1]);
            *(float2*)&C[(size_t)(r + 8) * N + c] = make_float2(acc[mt][nt][2], acc[mt][nt][3]);
        }
    }
}

// ---------------------------------------------------------------------------
// Host launcher (graph-capturable: kernel launches only).
// Inputs bound by element count (robust to metadata ordering); the two
// 3-element scale vectors keep encounter order (agscale first, wgscale second).
// ---------------------------------------------------------------------------
extern "C" void kernel_launch(void* const* d_in, const int* in_sizes, int n_in,
                              void* d_out, int out_size) {
    const float *hs = nullptr, *nw = nullptr, *w = nullptr;
    const float *ag = nullptr, *wg = nullptr;
    for (int i = 0; i < n_in; i++) {
        long sz = (long)in_sizes[i];
        if      (sz == (long)T_DIM * H_DIM)      hs = (const float*)d_in[i];
        else if (sz == 4L * H_DIM)               nw = (const float*)d_in[i];
        else if (sz == 3L * H_DIM * H_DIM)       w  = (const float*)d_in[i];
        else if (sz == 3) { if (!ag) ag = (const float*)d_in[i]; else wg = (const float*)d_in[i]; }
    }
    float* out = (float*)d_out;                // [8192, 4096] fp32

    dim3 rblk(256);
    dim3 ggrid(H_DIM / BN, T_DIM / BM);        // (32, 64)

    // x = relu(hs); resid = x; y = rmsnorm(x, nw[0]); quant(y, ag[0]) -> g_a
    rownorm_quant_kernel<<<T_DIM, rblk>>>(0, hs, nw, ag + 0,
                                          nullptr, nullptr, nullptr);

    for (int i = 0; i < 3; i++) {
        // quant(w[i], wg[i]) -> g_b   (bit-exact vs reference)
        wquant_kernel<<<H_DIM, rblk>>>(w + (size_t)i * H_DIM * H_DIM, wg + i);
        // g_z = g_a @ g_b^T (fp32 accum)
        gemm_kernel<<<ggrid, rblk>>>();
        if (i < 2) {
            // x = g_z*alpha + resid; resid = x; y = rmsnorm(x, nw[i+1]); quant -> g_a
            rownorm_quant_kernel<<<T_DIM, rblk>>>(1, nullptr, nw + (size_t)(i + 1) * H_DIM,
                                                  ag + (i + 1), wg + i, ag + i, nullptr);
        } else {
            // final: y = rmsnorm(g_z*alpha + resid, nw[3]) -> out (fp32)
            rownorm_quant_kernel<<<T_DIM, rblk>>>(2, nullptr, nw + (size_t)3 * H_DIM,
                                                  nullptr, wg + 2, ag + 2, out);
        }
    }
}

// round 5
// speedup vs baseline: 1.3814x; 1.3814x over previous
#include <cuda_runtime.h>
#include <cuda_fp16.h>
#include <cuda_bf16.h>
#include <cuda_fp8.h>
#include <cstdint>

// ---------------------------------------------------------------------------
// Problem constants
// ---------------------------------------------------------------------------
constexpr int T_DIM = 8192;
constexpr int H_DIM = 4096;
constexpr float EPS = 1e-6f;

// Scratch (static __device__ arrays; referenced from DEVICE code only —
// host-side use of these symbols passes the host shadow address, which
// GB300's ATS silently accepts -> silent wrong-memory writes).
__device__ float          g_resid[(size_t)T_DIM * H_DIM];   // 128 MB
__device__ float          g_z[(size_t)T_DIM * H_DIM];       // 128 MB
__device__ __nv_bfloat16  g_a[(size_t)T_DIM * H_DIM];       // 64 MB
__device__ __nv_bfloat16  g_b[(size_t)H_DIM * H_DIM];       // 32 MB

// ---------------------------------------------------------------------------
// PTX helpers (NO tcgen05 — base sm_103 target rejects it)
// ---------------------------------------------------------------------------
__device__ __forceinline__ uint32_t smem_u32_of(const void* p) {
    uint32_t a;
    asm("{ .reg .u64 t; cvta.to.shared.u64 t, %1; cvt.u32.u64 %0, t; }"
        : "=r"(a) : "l"(p));
    return a;
}
__device__ __forceinline__ void cp_async16(uint32_t saddr, const void* gaddr) {
    asm volatile("cp.async.cg.shared.global [%0], [%1], 16;" :: "r"(saddr), "l"(gaddr));
}
__device__ __forceinline__ void cp_commit() { asm volatile("cp.async.commit_group;"); }

__device__ __forceinline__ void ldsm_x4(uint32_t* r, uint32_t addr) {
    asm volatile("ldmatrix.sync.aligned.m8n8.x4.shared.b16 {%0,%1,%2,%3}, [%4];"
                 : "=r"(r[0]), "=r"(r[1]), "=r"(r[2]), "=r"(r[3]) : "r"(addr));
}
__device__ __forceinline__ void mma16816(float* d, const uint32_t* a, const uint32_t* b) {
    asm volatile(
        "mma.sync.aligned.m16n8k16.row.col.f32.bf16.bf16.f32 "
        "{%0,%1,%2,%3}, {%4,%5,%6,%7}, {%8,%9}, {%0,%1,%2,%3};"
        : "+f"(d[0]), "+f"(d[1]), "+f"(d[2]), "+f"(d[3])
        : "r"(a[0]), "r"(a[1]), "r"(a[2]), "r"(a[3]), "r"(b[0]), "r"(b[1]));
}

// ---------------------------------------------------------------------------
// Quantization emulation (division-free; exact threshold compares)
// ---------------------------------------------------------------------------
__device__ __forceinline__ float fp8_e4m3_round(float x) {
    __nv_fp8_storage_t r = __nv_cvt_float_to_fp8(x, __NV_SATFINITE, __NV_E4M3);
    __half_raw hr = __nv_cvt_fp8_to_halfraw(r, __NV_E4M3);
    return __half2float(__half(hr));
}

// One 16-element block -> 32B of dequantized bf16 (2x uint4).
// fl(y*gs)/sc >= mid  <=>  fl(y*gs) >= mid*sc   (mid*sc exact: <=3b x <=4b mantissa)
__device__ __forceinline__ void quant_block16(const float* y, float gs, uint4* out) {
    float amax = 0.0f;
#pragma unroll
    for (int j = 0; j < 16; j++) amax = fmaxf(amax, fabsf(y[j]));
    float sc = fminf(__fmul_rn(__fdiv_rn(amax, 6.0f), gs), 448.0f);
    sc = fp8_e4m3_round(sc);
    const float t0 = 0.25f * sc, t1 = 0.75f * sc, t2 = 1.25f * sc, t3 = 1.75f * sc;
    const float t4 = 2.5f * sc, t5 = 3.5f * sc, t6 = 5.0f * sc;
    uint32_t p[8];
#pragma unroll
    for (int jj = 0; jj < 8; jj++) {
        float d[2];
#pragma unroll
        for (int h = 0; h < 2; h++) {
            float yv = y[jj * 2 + h];
            float a = fabsf(__fmul_rn(yv, gs));
            float q = 0.0f;
            q += (a >= t0) ? 0.5f : 0.0f;
            q += (a >= t1) ? 0.5f : 0.0f;
            q += (a >= t2) ? 0.5f : 0.0f;
            q += (a >= t3) ? 0.5f : 0.0f;
            q += (a >= t4) ? 1.0f : 0.0f;
            q += (a >= t5) ? 1.0f : 0.0f;
            q += (a >= t6) ? 2.0f : 0.0f;
            d[h] = copysignf(__fmul_rn(q, sc), yv);   // exact in bf16
        }
        __nv_bfloat162 b2 = __floats2bfloat162_rn(d[0], d[1]);
        p[jj] = *(uint32_t*)&b2;
    }
    out[0] = make_uint4(p[0], p[1], p[2], p[3]);
    out[1] = make_uint4(p[4], p[5], p[6], p[7]);
}

// ---------------------------------------------------------------------------
// Fused rownorm kernel: one block (256 threads) per row. Padded smem (17).
//   mode 0: x = relu(src);           resid=x; y=rmsnorm(x); quant->g_a
//   mode 1: x = g_z*alpha + g_resid; resid=x; y=rmsnorm(x); quant->g_a
//   mode 2: x = g_z*alpha + g_resid;          y=rmsnorm(x); y(f32)->yout
// ---------------------------------------------------------------------------
__global__ __launch_bounds__(256)
void rownorm_quant_kernel(int mode,
                          const float* __restrict__ src,
                          const float* __restrict__ norm_w,
                          const float* __restrict__ a_gs,
                          const float* __restrict__ wg_prev,
                          const float* __restrict__ ag_prev,
                          float* __restrict__ yout) {
    __shared__ float sx[256 * 17];
    __shared__ float warpsum[8];
    __shared__ float s_rstd;

    const int row = blockIdx.x;
    const int tid = threadIdx.x;
    const size_t base = (size_t)row * H_DIM;

    float alpha = 0.0f;
    if (mode != 0)
        alpha = __fdiv_rn(1.0f, __fmul_rn(*wg_prev, *ag_prev));

    float ss = 0.0f;
#pragma unroll
    for (int t = 0; t < 4; t++) {
        int v = tid + t * 256;                 // float4 index within row
        float4 x4;
        if (mode == 0) {
            float4 s = ((const float4*)(src + base))[v];
            x4 = make_float4(fmaxf(s.x, 0.f), fmaxf(s.y, 0.f),
                             fmaxf(s.z, 0.f), fmaxf(s.w, 0.f));
        } else {
            float4 z = ((const float4*)(g_z + base))[v];
            float4 r = ((const float4*)(g_resid + base))[v];
            x4.x = __fadd_rn(__fmul_rn(z.x, alpha), r.x);
            x4.y = __fadd_rn(__fmul_rn(z.y, alpha), r.y);
            x4.z = __fadd_rn(__fmul_rn(z.z, alpha), r.z);
            x4.w = __fadd_rn(__fmul_rn(z.w, alpha), r.w);
        }
        if (mode != 2) ((float4*)(g_resid + base))[v] = x4;
        ss = fmaf(x4.x, x4.x, fmaf(x4.y, x4.y, fmaf(x4.z, x4.z, fmaf(x4.w, x4.w, ss))));
        float* p = &sx[(v >> 2) * 17 + (v & 3) * 4];
        p[0] = x4.x; p[1] = x4.y; p[2] = x4.z; p[3] = x4.w;
    }

#pragma unroll
    for (int o = 16; o > 0; o >>= 1) ss += __shfl_xor_sync(0xffffffffu, ss, o);
    if ((tid & 31) == 0) warpsum[tid >> 5] = ss;
    __syncthreads();
    if (tid == 0) {
        float t = 0.0f;
#pragma unroll
        for (int i = 0; i < 8; i++) t += warpsum[i];
        float mean = t * (1.0f / (float)H_DIM);
        s_rstd = __frsqrt_rn(__fadd_rn(mean, EPS));
    }
    __syncthreads();
    const float rstd = s_rstd;

    float y[16];
    const float4* nw4 = (const float4*)(norm_w + tid * 16);
#pragma unroll
    for (int q = 0; q < 4; q++) {
        float4 wv = nw4[q];
        y[q * 4 + 0] = __fmul_rn(__fmul_rn(sx[tid * 17 + q * 4 + 0], rstd), wv.x);
        y[q * 4 + 1] = __fmul_rn(__fmul_rn(sx[tid * 17 + q * 4 + 1], rstd), wv.y);
        y[q * 4 + 2] = __fmul_rn(__fmul_rn(sx[tid * 17 + q * 4 + 2], rstd), wv.z);
        y[q * 4 + 3] = __fmul_rn(__fmul_rn(sx[tid * 17 + q * 4 + 3], rstd), wv.w);
    }
    if (mode == 2) {
        float4* o4 = (float4*)(yout + base + tid * 16);
#pragma unroll
        for (int q = 0; q < 4; q++)
            o4[q] = make_float4(y[q * 4], y[q * 4 + 1], y[q * 4 + 2], y[q * 4 + 3]);
    } else {
        uint4 o[2];
        quant_block16(y, *a_gs, o);
        uint4* dst = (uint4*)(g_a + base + tid * 16);
        dst[0] = o[0]; dst[1] = o[1];
    }
}

// ---------------------------------------------------------------------------
// Weight quantization: one block per weight row.
// ---------------------------------------------------------------------------
__global__ __launch_bounds__(256)
void wquant_kernel(const float* __restrict__ w, const float* __restrict__ gs_ptr) {
    const int row = blockIdx.x;
    const int tid = threadIdx.x;
    const size_t base = (size_t)row * H_DIM;
    float y[16];
    const float4* src = (const float4*)(w + base + tid * 16);
#pragma unroll
    for (int q = 0; q < 4; q++) {
        float4 v = src[q];
        y[q * 4 + 0] = v.x; y[q * 4 + 1] = v.y; y[q * 4 + 2] = v.z; y[q * 4 + 3] = v.w;
    }
    uint4 o[2];
    quant_block16(y, *gs_ptr, o);
    uint4* dst = (uint4*)(g_b + base + tid * 16);
    dst[0] = o[0]; dst[1] = o[1];
}

// ---------------------------------------------------------------------------
// bf16 GEMM via mma.sync: g_z[t][n] = sum_k g_a[t][k] * g_b[n][k]
// CTA 128x256, 8 warps of 64x64, BK=32, 4-stage cp.async, ldmatrix.x4 frags.
// smem rows padded to 80B: LDSM rows hit banks {0,20,8,28,16,4,24,12} -> CF.
// ---------------------------------------------------------------------------
constexpr int BM = 128, BN = 256, BK = 32, STAGES = 4;
constexpr int SROW_B = 80;                         // bytes per smem row
constexpr int A_STAGE_BYTES = BM * SROW_B;         // 10240
constexpr int B_STAGE_BYTES = BN * SROW_B;         // 20480
constexpr int STAGE_BYTES = A_STAGE_BYTES + B_STAGE_BYTES;  // 30720
constexpr int GEMM_SMEM = STAGES * STAGE_BYTES;    // 122880

__global__ __launch_bounds__(256, 1)
void gemm_kernel() {
    const __nv_bfloat16* __restrict__ A = g_a;
    const __nv_bfloat16* __restrict__ B = g_b;
    float* __restrict__ C = g_z;
    constexpr int K = H_DIM, N = H_DIM;

    extern __shared__ __align__(128) char smem[];
    const uint32_t smem_u32 = smem_u32_of(smem);

    const int tid = threadIdx.x;
    const int lane = tid & 31, wid = tid >> 5;
    const int blockM = blockIdx.y * BM;
    const int blockN = blockIdx.x * BN;
    const __nv_bfloat16* Abase = A + (size_t)blockM * K;
    const __nv_bfloat16* Bbase = B + (size_t)blockN * K;

    // warp tile: 64x64; warp grid 2 (M) x 4 (N)
    const int wm = (wid & 1) * 64;
    const int wn = (wid >> 1) * 64;
    const int g  = lane >> 2;          // 0..7
    const int t4 = lane & 3;           // 0..3

    // ldmatrix per-lane address components
    const int a_row_in = (lane & 15);              // row within m16 tile
    const int a_koff   = (lane >> 4) << 3;         // 0 or 8
    const int b_nrow   = (lane & 7) + ((lane >> 4) << 3);  // n row within 16-wide pair
    const int b_koff   = ((lane >> 3) & 1) << 3;   // 0 or 8

    float acc[4][8][4];
#pragma unroll
    for (int mt = 0; mt < 4; mt++)
#pragma unroll
        for (int nt = 0; nt < 8; nt++)
#pragma unroll
            for (int r = 0; r < 4; r++) acc[mt][nt][r] = 0.0f;

    auto load_stage = [&](int slot, int k0) {
        const uint32_t abase = smem_u32 + slot * STAGE_BYTES;
        const uint32_t bbase = abase + A_STAGE_BYTES;
#pragma unroll
        for (int t = 0; t < 2; t++) {              // A: 512 x 16B
            int chunk = tid + t * 256;
            int r = chunk >> 2, c = chunk & 3;
            cp_async16(abase + r * SROW_B + c * 16,
                       Abase + (size_t)r * K + k0 + c * 8);
        }
#pragma unroll
        for (int t = 0; t < 4; t++) {              // B: 1024 x 16B
            int chunk = tid + t * 256;
            int r = chunk >> 2, c = chunk & 3;
            cp_async16(bbase + r * SROW_B + c * 16,
                       Bbase + (size_t)r * K + k0 + c * 8);
        }
    };

    // prologue: stages 0..2
#pragma unroll
    for (int s = 0; s < STAGES - 1; s++) { load_stage(s, s * BK); cp_commit(); }

    const int KT = K / BK;   // 128
    for (int i = 0; i < KT; i++) {
        const int slot = i & (STAGES - 1);
        asm volatile("cp.async.wait_group %0;" :: "n"(STAGES - 2) : "memory");
        __syncthreads();

        if (i + STAGES - 1 < KT)
            load_stage((i + STAGES - 1) & (STAGES - 1), (i + STAGES - 1) * BK);
        cp_commit();   // real or empty: keeps exactly-3-pending invariant

        const uint32_t sa = smem_u32 + slot * STAGE_BYTES;
        const uint32_t sb = sa + A_STAGE_BYTES;
#pragma unroll
        for (int kk = 0; kk < BK; kk += 16) {
            uint32_t a_frag[4][4];
            uint32_t b_frag[8][2];
#pragma unroll
            for (int mt = 0; mt < 4; mt++) {
                int rowa = wm + mt * 16 + a_row_in;
                ldsm_x4(a_frag[mt], sa + rowa * SROW_B + (kk + a_koff) * 2);
            }
#pragma unroll
            for (int p = 0; p < 4; p++) {
                uint32_t r4[4];
                int rowb = wn + p * 16 + b_nrow;
                ldsm_x4(r4, sb + rowb * SROW_B + (kk + b_koff) * 2);
                b_frag[p * 2 + 0][0] = r4[0]; b_frag[p * 2 + 0][1] = r4[1];
                b_frag[p * 2 + 1][0] = r4[2]; b_frag[p * 2 + 1][1] = r4[3];
            }
#pragma unroll
            for (int mt = 0; mt < 4; mt++)
#pragma unroll
                for (int nt = 0; nt < 8; nt++)
                    mma16816(acc[mt][nt], a_frag[mt], b_frag[nt]);
        }
        __syncthreads();
    }

    // Epilogue: coalesced float2 stores
#pragma unroll
    for (int mt = 0; mt < 4; mt++) {
#pragma unroll
        for (int nt = 0; nt < 8; nt++) {
            int r = blockM + wm + mt * 16 + g;
            int c = blockN + wn + nt * 8 + t4 * 2;
            *(float2*)&C[(size_t)r * N + c]       = make_float2(acc[mt][nt][0], acc[mt][nt][1]);
            *(float2*)&C[(size_t)(r + 8) * N + c] = make_float2(acc[mt][nt][2], acc[mt][nt][3]);
        }
    }
}

// ---------------------------------------------------------------------------
// Host launcher (graph-capturable: kernel launches only)
// ---------------------------------------------------------------------------
extern "C" void kernel_launch(void* const* d_in, const int* in_sizes, int n_in,
                              void* d_out, int out_size) {
    const float *hs = nullptr, *nw = nullptr, *w = nullptr;
    const float *ag = nullptr, *wg = nullptr;
    for (int i = 0; i < n_in; i++) {
        long sz = (long)in_sizes[i];
        if      (sz == (long)T_DIM * H_DIM)      hs = (const float*)d_in[i];
        else if (sz == 4L * H_DIM)               nw = (const float*)d_in[i];
        else if (sz == 3L * H_DIM * H_DIM)       w  = (const float*)d_in[i];
        else if (sz == 3) { if (!ag) ag = (const float*)d_in[i]; else wg = (const float*)d_in[i]; }
    }
    float* out = (float*)d_out;                  // [8192, 4096] fp32

    cudaFuncSetAttribute(gemm_kernel,
                         cudaFuncAttributeMaxDynamicSharedMemorySize, GEMM_SMEM);

    dim3 rblk(256);
    dim3 ggrid(H_DIM / BN, T_DIM / BM);          // (16, 64)

    rownorm_quant_kernel<<<T_DIM, rblk>>>(0, hs, nw, ag + 0,
                                          nullptr, nullptr, nullptr);
    for (int i = 0; i < 3; i++) {
        wquant_kernel<<<H_DIM, rblk>>>(w + (size_t)i * H_DIM * H_DIM, wg + i);
        gemm_kernel<<<ggrid, rblk, GEMM_SMEM>>>();
        if (i < 2) {
            rownorm_quant_kernel<<<T_DIM, rblk>>>(1, nullptr, nw + (size_t)(i + 1) * H_DIM,
                                                  ag + (i + 1), wg + i, ag + i, nullptr);
        } else {
            rownorm_quant_kernel<<<T_DIM, rblk>>>(2, nullptr, nw + (size_t)3 * H_DIM,
                                                  nullptr, wg + 2, ag + 2, out);
        }
    }
}

// round 6
// speedup vs baseline: 1.5334x; 1.1101x over previous
#include <cuda_runtime.h>
#include <cuda_fp16.h>
#include <cuda_bf16.h>
#include <cuda_fp8.h>
#include <cstdint>

// ---------------------------------------------------------------------------
// Problem constants
// ---------------------------------------------------------------------------
constexpr int T_DIM = 8192;
constexpr int H_DIM = 4096;
constexpr float EPS = 1e-6f;

// Scratch (static __device__ arrays; referenced from DEVICE code only —
// host-side use of these symbols passes the host shadow address, which
// GB300's ATS silently accepts -> silent wrong-memory writes).
__device__ float          g_resid[(size_t)T_DIM * H_DIM];    // 128 MB (holds x)
__device__ float          g_ss_part[(size_t)T_DIM * 64];     // 2 MB row-ss partials
__device__ __nv_bfloat16  g_a[(size_t)T_DIM * H_DIM];        // 64 MB
__device__ __nv_bfloat16  g_b[(size_t)H_DIM * H_DIM];        // 32 MB

// ---------------------------------------------------------------------------
// PTX helpers (NO tcgen05 — harness PTX target is base sm_103)
// ---------------------------------------------------------------------------
__device__ __forceinline__ uint32_t smem_u32_of(const void* p) {
    uint32_t a;
    asm("{ .reg .u64 t; cvta.to.shared.u64 t, %1; cvt.u32.u64 %0, t; }"
        : "=r"(a) : "l"(p));
    return a;
}
__device__ __forceinline__ void cp_async16(uint32_t saddr, const void* gaddr) {
    asm volatile("cp.async.cg.shared.global [%0], [%1], 16;" :: "r"(saddr), "l"(gaddr));
}
__device__ __forceinline__ void cp_commit() { asm volatile("cp.async.commit_group;"); }

__device__ __forceinline__ void ldsm_x4(uint32_t* r, uint32_t addr) {
    asm volatile("ldmatrix.sync.aligned.m8n8.x4.shared.b16 {%0,%1,%2,%3}, [%4];"
                 : "=r"(r[0]), "=r"(r[1]), "=r"(r[2]), "=r"(r[3]) : "r"(addr));
}
__device__ __forceinline__ void mma16816(float* d, const uint32_t* a, const uint32_t* b) {
    asm volatile(
        "mma.sync.aligned.m16n8k16.row.col.f32.bf16.bf16.f32 "
        "{%0,%1,%2,%3}, {%4,%5,%6,%7}, {%8,%9}, {%0,%1,%2,%3};"
        : "+f"(d[0]), "+f"(d[1]), "+f"(d[2]), "+f"(d[3])
        : "r"(a[0]), "r"(a[1]), "r"(a[2]), "r"(a[3]), "r"(b[0]), "r"(b[1]));
}

// ---------------------------------------------------------------------------
// Quantization emulation (division-free; exact threshold compares)
// ---------------------------------------------------------------------------
__device__ __forceinline__ float fp8_e4m3_round(float x) {
    __nv_fp8_storage_t r = __nv_cvt_float_to_fp8(x, __NV_SATFINITE, __NV_E4M3);
    __half_raw hr = __nv_cvt_fp8_to_halfraw(r, __NV_E4M3);
    return __half2float(__half(hr));
}

// One 16-element block -> 32B of dequantized bf16 (2x uint4).
// fl(y*gs)/sc >= mid  <=>  fl(y*gs) >= mid*sc   (mid*sc exact: <=3b x <=4b mantissa)
__device__ __forceinline__ void quant_block16(const float* y, float gs, uint4* out) {
    float amax = 0.0f;
#pragma unroll
    for (int j = 0; j < 16; j++) amax = fmaxf(amax, fabsf(y[j]));
    float sc = fminf(__fmul_rn(__fdiv_rn(amax, 6.0f), gs), 448.0f);
    sc = fp8_e4m3_round(sc);
    const float t0 = 0.25f * sc, t1 = 0.75f * sc, t2 = 1.25f * sc, t3 = 1.75f * sc;
    const float t4 = 2.5f * sc, t5 = 3.5f * sc, t6 = 5.0f * sc;
    uint32_t p[8];
#pragma unroll
    for (int jj = 0; jj < 8; jj++) {
        float d[2];
#pragma unroll
        for (int h = 0; h < 2; h++) {
            float yv = y[jj * 2 + h];
            float a = fabsf(__fmul_rn(yv, gs));
            float q = 0.0f;
            q += (a >= t0) ? 0.5f : 0.0f;
            q += (a >= t1) ? 0.5f : 0.0f;
            q += (a >= t2) ? 0.5f : 0.0f;
            q += (a >= t3) ? 0.5f : 0.0f;
            q += (a >= t4) ? 1.0f : 0.0f;
            q += (a >= t5) ? 1.0f : 0.0f;
            q += (a >= t6) ? 2.0f : 0.0f;
            d[h] = copysignf(__fmul_rn(q, sc), yv);   // exact in bf16
        }
        __nv_bfloat162 b2 = __floats2bfloat162_rn(d[0], d[1]);
        p[jj] = *(uint32_t*)&b2;
    }
    out[0] = make_uint4(p[0], p[1], p[2], p[3]);
    out[1] = make_uint4(p[4], p[5], p[6], p[7]);
}

// ---------------------------------------------------------------------------
// First layer prologue: x = relu(hs); resid = x; y = rmsnorm(x, w0); quant->g_a
// One block per row, 256 threads; regs-only (thread owns its 16-elem block).
// ---------------------------------------------------------------------------
__global__ __launch_bounds__(256)
void rownorm0_kernel(const float* __restrict__ src,
                     const float* __restrict__ norm_w,
                     const float* __restrict__ a_gs) {
    __shared__ float warpsum[8];
    __shared__ float s_rstd;
    const int row = blockIdx.x;
    const int tid = threadIdx.x;
    const size_t base = (size_t)row * H_DIM;

    float x[16];
    float ss = 0.0f;
    const float4* s4 = (const float4*)(src + base + tid * 16);
    float4* r4 = (float4*)(g_resid + base + tid * 16);
#pragma unroll
    for (int q = 0; q < 4; q++) {
        float4 s = s4[q];
        float4 xv = make_float4(fmaxf(s.x, 0.f), fmaxf(s.y, 0.f),
                                fmaxf(s.z, 0.f), fmaxf(s.w, 0.f));
        r4[q] = xv;
        x[q * 4 + 0] = xv.x; x[q * 4 + 1] = xv.y; x[q * 4 + 2] = xv.z; x[q * 4 + 3] = xv.w;
        ss = fmaf(xv.x, xv.x, fmaf(xv.y, xv.y, fmaf(xv.z, xv.z, fmaf(xv.w, xv.w, ss))));
    }
#pragma unroll
    for (int o = 16; o > 0; o >>= 1) ss += __shfl_xor_sync(0xffffffffu, ss, o);
    if ((tid & 31) == 0) warpsum[tid >> 5] = ss;
    __syncthreads();
    if (tid == 0) {
        float t = 0.0f;
#pragma unroll
        for (int i = 0; i < 8; i++) t += warpsum[i];
        s_rstd = __frsqrt_rn(__fadd_rn(t * (1.0f / (float)H_DIM), EPS));
    }
    __syncthreads();
    const float rstd = s_rstd;

    float y[16];
    const float4* nw4 = (const float4*)(norm_w + tid * 16);
#pragma unroll
    for (int q = 0; q < 4; q++) {
        float4 wv = nw4[q];
        y[q * 4 + 0] = __fmul_rn(__fmul_rn(x[q * 4 + 0], rstd), wv.x);
        y[q * 4 + 1] = __fmul_rn(__fmul_rn(x[q * 4 + 1], rstd), wv.y);
        y[q * 4 + 2] = __fmul_rn(__fmul_rn(x[q * 4 + 2], rstd), wv.z);
        y[q * 4 + 3] = __fmul_rn(__fmul_rn(x[q * 4 + 3], rstd), wv.w);
    }
    uint4 o[2];
    quant_block16(y, *a_gs, o);
    uint4* dst = (uint4*)(g_a + base + tid * 16);
    dst[0] = o[0]; dst[1] = o[1];
}

// ---------------------------------------------------------------------------
// Weight quantization: one block per weight row.
// ---------------------------------------------------------------------------
__global__ __launch_bounds__(256)
void wquant_kernel(const float* __restrict__ w, const float* __restrict__ gs_ptr) {
    const int row = blockIdx.x;
    const int tid = threadIdx.x;
    const size_t base = (size_t)row * H_DIM;
    float y[16];
    const float4* src = (const float4*)(w + base + tid * 16);
#pragma unroll
    for (int q = 0; q < 4; q++) {
        float4 v = src[q];
        y[q * 4 + 0] = v.x; y[q * 4 + 1] = v.y; y[q * 4 + 2] = v.z; y[q * 4 + 3] = v.w;
    }
    uint4 o[2];
    quant_block16(y, *gs_ptr, o);
    uint4* dst = (uint4*)(g_b + base + tid * 16);
    dst[0] = o[0]; dst[1] = o[1];
}

// ---------------------------------------------------------------------------
// bf16 GEMM + fused residual epilogue.
//   acc = g_a @ g_b^T; x = fl(acc*alpha) + resid; g_resid <- x;
//   g_ss_part[row][slot] <- per-warp partial sum of x^2 (deterministic).
// CTA 128x256, 8 warps of 64x64, BK=32, 4-stage cp.async, ldmatrix.x4,
// double register-buffered fragments, ONE __syncthreads per iter.
// smem rows padded to 80B -> LDSM phases hit all 32 banks (conflict-free).
// ---------------------------------------------------------------------------
constexpr int BM = 128, BN = 256, BK = 32, STAGES = 4;
constexpr int SROW_B = 80;
constexpr int A_STAGE_BYTES = BM * SROW_B;                  // 10240
constexpr int B_STAGE_BYTES = BN * SROW_B;                  // 20480
constexpr int STAGE_BYTES = A_STAGE_BYTES + B_STAGE_BYTES;  // 30720
constexpr int GEMM_SMEM = STAGES * STAGE_BYTES;             // 122880

__global__ __launch_bounds__(256, 1)
void gemm_kernel(const float* __restrict__ wg, const float* __restrict__ ag) {
    const __nv_bfloat16* __restrict__ A = g_a;
    const __nv_bfloat16* __restrict__ B = g_b;
    constexpr int K = H_DIM, N = H_DIM;

    extern __shared__ __align__(128) char smem[];
    const uint32_t smem_u32 = smem_u32_of(smem);

    const int tid = threadIdx.x;
    const int lane = tid & 31, wid = tid >> 5;
    const int blockM = blockIdx.y * BM;
    const int blockN = blockIdx.x * BN;
    const __nv_bfloat16* Abase = A + (size_t)blockM * K;
    const __nv_bfloat16* Bbase = B + (size_t)blockN * K;

    const float alpha = __fdiv_rn(1.0f, __fmul_rn(*wg, *ag));

    // warp tile 64x64; warp grid 2 (M) x 4 (N)
    const int wm = (wid & 1) * 64;
    const int wn = (wid >> 1) * 64;
    const int g  = lane >> 2;
    const int t4 = lane & 3;

    const int a_row_in = (lane & 15);
    const int a_koff   = (lane >> 4) << 3;
    const int b_nrow   = (lane & 7) + ((lane >> 4) << 3);
    const int b_koff   = ((lane >> 3) & 1) << 3;

    float acc[4][8][4];
#pragma unroll
    for (int mt = 0; mt < 4; mt++)
#pragma unroll
        for (int nt = 0; nt < 8; nt++)
#pragma unroll
            for (int r = 0; r < 4; r++) acc[mt][nt][r] = 0.0f;

    auto load_stage = [&](int slot, int k0) {
        const uint32_t abase = smem_u32 + slot * STAGE_BYTES;
        const uint32_t bbase = abase + A_STAGE_BYTES;
#pragma unroll
        for (int t = 0; t < 2; t++) {
            int chunk = tid + t * 256;
            int r = chunk >> 2, c = chunk & 3;
            cp_async16(abase + r * SROW_B + c * 16, Abase + (size_t)r * K + k0 + c * 8);
        }
#pragma unroll
        for (int t = 0; t < 4; t++) {
            int chunk = tid + t * 256;
            int r = chunk >> 2, c = chunk & 3;
            cp_async16(bbase + r * SROW_B + c * 16, Bbase + (size_t)r * K + k0 + c * 8);
        }
    };

#pragma unroll
    for (int s = 0; s < STAGES - 1; s++) { load_stage(s, s * BK); cp_commit(); }
    asm volatile("cp.async.wait_group %0;" :: "n"(STAGES - 2) : "memory");
    __syncthreads();

    const int KT = K / BK;   // 128
    for (int i = 0; i < KT; i++) {
        const int slot = i & (STAGES - 1);
        const uint32_t sa = smem_u32 + slot * STAGE_BYTES;
        const uint32_t sb = sa + A_STAGE_BYTES;

        // --- all fragment loads for both K16 halves, issued back-to-back
        uint32_t a0[4][4], a1[4][4], b0[8][2], b1[8][2];
#pragma unroll
        for (int mt = 0; mt < 4; mt++) {
            const uint32_t ra = sa + (wm + mt * 16 + a_row_in) * SROW_B;
            ldsm_x4(a0[mt], ra + (0 + a_koff) * 2);
            ldsm_x4(a1[mt], ra + (16 + a_koff) * 2);
        }
#pragma unroll
        for (int p = 0; p < 4; p++) {
            const uint32_t rb = sb + (wn + p * 16 + b_nrow) * SROW_B;
            uint32_t r4[4];
            ldsm_x4(r4, rb + (0 + b_koff) * 2);
            b0[p * 2 + 0][0] = r4[0]; b0[p * 2 + 0][1] = r4[1];
            b0[p * 2 + 1][0] = r4[2]; b0[p * 2 + 1][1] = r4[3];
            ldsm_x4(r4, rb + (16 + b_koff) * 2);
            b1[p * 2 + 0][0] = r4[0]; b1[p * 2 + 0][1] = r4[1];
            b1[p * 2 + 1][0] = r4[2]; b1[p * 2 + 1][1] = r4[3];
        }

        // --- next stage global loads (hidden under the MMAs below)
        if (i + STAGES - 1 < KT)
            load_stage((i + STAGES - 1) & (STAGES - 1), (i + STAGES - 1) * BK);
        cp_commit();   // real or empty: keeps exactly-3-pending invariant

        // --- MMAs
#pragma unroll
        for (int mt = 0; mt < 4; mt++)
#pragma unroll
            for (int nt = 0; nt < 8; nt++)
                mma16816(acc[mt][nt], a0[mt], b0[nt]);
#pragma unroll
        for (int mt = 0; mt < 4; mt++)
#pragma unroll
            for (int nt = 0; nt < 8; nt++)
                mma16816(acc[mt][nt], a1[mt], b1[nt]);

        asm volatile("cp.async.wait_group %0;" :: "n"(STAGES - 2) : "memory");
        __syncthreads();
    }

    // --- Fused epilogue: x = fl(z*alpha)+resid -> g_resid; row-ss partials
    const int wnIdx = wid >> 1;            // 0..3
#pragma unroll
    for (int mt = 0; mt < 4; mt++) {
        const int r0 = blockM + wm + mt * 16 + g;
        float* p0 = g_resid + (size_t)r0 * N + blockN + wn;
        float* p1 = p0 + (size_t)8 * N;
        float s0 = 0.0f, s1 = 0.0f;
#pragma unroll
        for (int nt = 0; nt < 8; nt++) {
            const int c = nt * 8 + t4 * 2;
            float2 v0 = *(float2*)(p0 + c);
            float2 v1 = *(float2*)(p1 + c);
            float x00 = __fadd_rn(__fmul_rn(acc[mt][nt][0], alpha), v0.x);
            float x01 = __fadd_rn(__fmul_rn(acc[mt][nt][1], alpha), v0.y);
            float x10 = __fadd_rn(__fmul_rn(acc[mt][nt][2], alpha), v1.x);
            float x11 = __fadd_rn(__fmul_rn(acc[mt][nt][3], alpha), v1.y);
            *(float2*)(p0 + c) = make_float2(x00, x01);
            *(float2*)(p1 + c) = make_float2(x10, x11);
            s0 = fmaf(x00, x00, fmaf(x01, x01, s0));
            s1 = fmaf(x10, x10, fmaf(x11, x11, s1));
        }
        // quad-reduce across t4 lanes (deterministic fixed order)
        s0 += __shfl_xor_sync(0xffffffffu, s0, 1);
        s0 += __shfl_xor_sync(0xffffffffu, s0, 2);
        s1 += __shfl_xor_sync(0xffffffffu, s1, 1);
        s1 += __shfl_xor_sync(0xffffffffu, s1, 2);
        if (t4 == 0) {
            const int slot = blockIdx.x * 4 + wnIdx;
            g_ss_part[(size_t)r0 * 64 + slot]       = s0;
            g_ss_part[(size_t)(r0 + 8) * 64 + slot] = s1;
        }
    }
}

// ---------------------------------------------------------------------------
// Post-GEMM norm: rstd from precomputed partials; normalize + quant (or emit).
// ---------------------------------------------------------------------------
__global__ __launch_bounds__(256)
void normquant_kernel(const float* __restrict__ norm_w,
                      const float* __restrict__ a_gs,
                      float* __restrict__ yout, int final_out) {
    __shared__ float sred[2];
    const int row = blockIdx.x;
    const int tid = threadIdx.x;
    const size_t base = (size_t)row * H_DIM;

    float v = 0.0f;
    if (tid < 64) v = g_ss_part[(size_t)row * 64 + tid];
#pragma unroll
    for (int o = 16; o > 0; o >>= 1) v += __shfl_xor_sync(0xffffffffu, v, o);
    if (tid == 0)  sred[0] = v;
    if (tid == 32) sred[1] = v;
    __syncthreads();
    const float ss = __fadd_rn(sred[0], sred[1]);
    const float rstd = __frsqrt_rn(__fadd_rn(ss * (1.0f / (float)H_DIM), EPS));

    float y[16];
    const float4* xs  = (const float4*)(g_resid + base + tid * 16);
    const float4* nw4 = (const float4*)(norm_w + tid * 16);
#pragma unroll
    for (int q = 0; q < 4; q++) {
        float4 xv = xs[q];
        float4 wv = nw4[q];
        y[q * 4 + 0] = __fmul_rn(__fmul_rn(xv.x, rstd), wv.x);
        y[q * 4 + 1] = __fmul_rn(__fmul_rn(xv.y, rstd), wv.y);
        y[q * 4 + 2] = __fmul_rn(__fmul_rn(xv.z, rstd), wv.z);
        y[q * 4 + 3] = __fmul_rn(__fmul_rn(xv.w, rstd), wv.w);
    }
    if (final_out) {
        float4* o4 = (float4*)(yout + base + tid * 16);
#pragma unroll
        for (int q = 0; q < 4; q++)
            o4[q] = make_float4(y[q * 4], y[q * 4 + 1], y[q * 4 + 2], y[q * 4 + 3]);
    } else {
        uint4 o[2];
        quant_block16(y, *a_gs, o);
        uint4* dst = (uint4*)(g_a + base + tid * 16);
        dst[0] = o[0]; dst[1] = o[1];
    }
}

// ---------------------------------------------------------------------------
// Host launcher (graph-capturable: kernel launches only)
// ---------------------------------------------------------------------------
extern "C" void kernel_launch(void* const* d_in, const int* in_sizes, int n_in,
                              void* d_out, int out_size) {
    const float *hs = nullptr, *nw = nullptr, *w = nullptr;
    const float *ag = nullptr, *wg = nullptr;
    for (int i = 0; i < n_in; i++) {
        long sz = (long)in_sizes[i];
        if      (sz == (long)T_DIM * H_DIM)      hs = (const float*)d_in[i];
        else if (sz == 4L * H_DIM)               nw = (const float*)d_in[i];
        else if (sz == 3L * H_DIM * H_DIM)       w  = (const float*)d_in[i];
        else if (sz == 3) { if (!ag) ag = (const float*)d_in[i]; else wg = (const float*)d_in[i]; }
    }
    float* out = (float*)d_out;                  // [8192, 4096] fp32

    cudaFuncSetAttribute(gemm_kernel,
                         cudaFuncAttributeMaxDynamicSharedMemorySize, GEMM_SMEM);

    dim3 rblk(256);
    dim3 ggrid(H_DIM / BN, T_DIM / BM);          // (16, 64)

    rownorm0_kernel<<<T_DIM, rblk>>>(hs, nw, ag + 0);
    for (int i = 0; i < 3; i++) {
        wquant_kernel<<<H_DIM, rblk>>>(w + (size_t)i * H_DIM * H_DIM, wg + i);
        gemm_kernel<<<ggrid, rblk, GEMM_SMEM>>>(wg + i, ag + i);
        if (i < 2) {
            normquant_kernel<<<T_DIM, rblk>>>(nw + (size_t)(i + 1) * H_DIM,
                                              ag + (i + 1), nullptr, 0);
        } else {
            normquant_kernel<<<T_DIM, rblk>>>(nw + (size_t)3 * H_DIM,
                                              nullptr, out, 1);
        }
    }
}